// round 12
// baseline (speedup 1.0000x reference)
#include <cuda_runtime.h>
#include <cuda_fp16.h>
#include <math.h>

// Problem dims
#define Nb 64
#define Tt 512
#define Ii 512
#define Hh 1024
#define Oo 512
#define MROWS (Nb*Tt)
#define NH (Nb*Hh)
#define RNN_NCTA 128

typedef unsigned long long ull;

// ---------------- scratch ----------------
__device__ float  g_nmaj [(size_t)Tt * NH];      // n-major staging [T][N][H]
__device__ float  g_inpT [(size_t)Tt * NH];      // transposed inp [T][H][64] fp32
__device__ __half g_hsT  [(size_t)Tt * NH];      // fp16 transposed h [T][1024][64]
__device__ float  g_tmp  [(size_t)Tt * Nb * Oo];
__device__ float  g_out_t[(size_t)Tt * Nb * Oo];
__device__ __half g_h0T  [NH];
__device__ __half g_h0T2 [NH];
__device__ unsigned g_l1[16 * 32];
__device__ unsigned g_l2;
__device__ volatile unsigned g_gen[16 * 32];

// ---------------- helpers ----------------
__device__ __forceinline__ ull ffma2(ull a, ull b, ull c) {
    ull d;
    asm("fma.rn.f32x2 %0, %1, %2, %3;" : "=l"(d) : "l"(a), "l"(b), "l"(c));
    return d;
}
__device__ __forceinline__ ull addf2(ull a, ull b) {
    ull d;
    asm("add.rn.f32x2 %0, %1, %2;" : "=l"(d) : "l"(a), "l"(b));
    return d;
}
__device__ __forceinline__ float2 unpack2(ull v) {
    float2 r;
    asm("mov.b64 {%0, %1}, %2;" : "=f"(r.x), "=f"(r.y) : "l"(v));
    return r;
}
__device__ __forceinline__ ull dup2(float v) {
    ull r;
    asm("mov.b64 %0, {%1, %1};" : "=l"(r) : "f"(v));
    return r;
}
// 2 packed fp16 -> f32x2
__device__ __forceinline__ ull hf2f(unsigned v) {
    __half2 h = *reinterpret_cast<__half2*>(&v);
    float2 f = __half22float2(h);
    ull d;
    asm("mov.b64 %0, {%1, %2};" : "=l"(d) : "f"(f.x), "f"(f.y));
    return d;
}
__device__ __forceinline__ float retanh(float x) {
    return x > 0.f ? tanhf(x) : 0.f;
}
__device__ __forceinline__ unsigned smem_u32(const void* p) {
    return (unsigned)__cvta_generic_to_shared(p);
}
#define CP_ASYNC16(dst, src) \
    asm volatile("cp.async.cg.shared.global [%0], [%1], 16;" :: "r"(dst), "l"(src))
#define CP_COMMIT() asm volatile("cp.async.commit_group;" ::: "memory")
__device__ __forceinline__ void cp_wait_n(int n) {
    if (n == 0)      asm volatile("cp.async.wait_group 0;" ::: "memory");
    else if (n == 1) asm volatile("cp.async.wait_group 1;" ::: "memory");
    else             asm volatile("cp.async.wait_group 2;" ::: "memory");
}

__global__ void reset_barrier_kernel() {
    int t = threadIdx.x;
    if (t < 16 * 32) { g_l1[t] = 0u; g_gen[t] = 0u; }
    if (t == 0) g_l2 = 0u;
}

// tree arrival + fan-out release (16 gen lines, 8 pollers each)
__device__ __forceinline__ void tree_barrier(int bx, unsigned target) {
    __syncthreads();
    if (threadIdx.x == 0) {
        __threadfence();
        unsigned o1 = atomicAdd(&g_l1[(bx >> 3) * 32], 1u);
        if ((o1 & 7u) == 7u) {
            unsigned o2 = atomicAdd(&g_l2, 1u);
            if ((o2 & 15u) == 15u) {
                __threadfence();
#pragma unroll
                for (int g = 0; g < 16; g++) g_gen[g * 32] = target;
            }
        }
        while (g_gen[(bx >> 3) * 32] < target) { }
        __threadfence();
    }
    __syncthreads();
}

// h0 [N][H] -> fp16 [H][64]
__global__ void transpose_h0(const float* __restrict__ in, __half* __restrict__ out) {
    int i = blockIdx.x * 256 + threadIdx.x;
    int h = i >> 6, n = i & 63;
    out[i] = __float2half(in[n * Hh + h]);
}

// inp [T][N][H] -> [T][H][64] fp32
__global__ void __launch_bounds__(256) transpose_inp(
    const float* __restrict__ in, float* __restrict__ out)
{
    __shared__ float s[32][65];
    const int t = blockIdx.x;
    const int h0 = blockIdx.y * 32;
    const int tid = threadIdx.x;
    const float* ip = in + (size_t)t * NH;
    float* op = out + (size_t)t * NH;

    int hl = tid & 31;
    int nb = tid >> 5;
#pragma unroll
    for (int i = 0; i < 8; i++) {
        int n = nb * 8 + i;
        s[hl][n] = ip[(size_t)n * Hh + h0 + hl];
    }
    __syncthreads();
    int n4 = (tid & 15) * 4;
    int hr = tid >> 4;
#pragma unroll
    for (int i = 0; i < 2; i++) {
        int h = hr * 2 + i;
        float4 v = make_float4(s[h][n4], s[h][n4 + 1], s[h][n4 + 2], s[h][n4 + 3]);
        *(float4*)(op + (size_t)(h0 + h) * Nb + n4) = v;
    }
}

// ---------------- GEMM: C = act(A * W^T + bias) ----------------
// AMAP : A rows gathered from data [N][T][I]
// ATMAP: A is fp16 [T][K][64] transposed: row r=(t*64+n), elem k at t*K*64+k*64+n
// CMAP : C rows written to [N][T][O]
template<int AMAP, int ATMAP, int CMAP, int RET>
__global__ void __launch_bounds__(256, 2) gemm128(
    const float* __restrict__ A, const float* __restrict__ W,
    const float* __restrict__ bias, float* __restrict__ C,
    int M, int Nc, int K)
{
    __shared__ float As[8][128];
    __shared__ float Bs[8][128];

    const int tid = threadIdx.x;
    const int m0 = blockIdx.x * 128;
    const int n0 = blockIdx.y * 128;

    const int warp = tid >> 5;
    const int lane = tid & 31;
    const int wm = warp & 3;
    const int wn = warp >> 2;
    const int tm = lane & 3;
    const int tn = lane >> 2;

    const int srow = tid >> 1;
    const int sk = (tid & 1) * 4;

    int r = m0 + srow;
    const float* Ap = 0;
    const __half* Abp = 0;
    if (AMAP) {
        int nn = r & 63, tt = r >> 6;
        Ap = A + (size_t)(nn * Tt + tt) * K + sk;
    } else if (ATMAP) {
        Abp = (const __half*)A + (size_t)(r >> 6) * K * Nb + (r & 63) + (size_t)sk * Nb;
    } else {
        Ap = A + (size_t)r * K + sk;
    }
    const float* Wp = W + (size_t)(n0 + srow) * K + sk;

    ull acc[4][8];
#pragma unroll
    for (int i = 0; i < 4; i++)
#pragma unroll
        for (int j = 0; j < 8; j++) acc[i][j] = 0ull;

    float4 av;
    if (ATMAP) {
        av.x = __half2float(Abp[0]);
        av.y = __half2float(Abp[Nb]);
        av.z = __half2float(Abp[2 * Nb]);
        av.w = __half2float(Abp[3 * Nb]);
    } else {
        av = *(const float4*)(Ap);
    }
    float4 wv = *(const float4*)(Wp);

    const int aoff = wm * 32 + tm * 8;
    const int boff = wn * 64 + tn * 8;

    for (int k0 = 0; k0 < K; k0 += 8) {
        As[sk + 0][srow] = av.x;
        As[sk + 1][srow] = av.y;
        As[sk + 2][srow] = av.z;
        As[sk + 3][srow] = av.w;
        Bs[sk + 0][srow] = wv.x;
        Bs[sk + 1][srow] = wv.y;
        Bs[sk + 2][srow] = wv.z;
        Bs[sk + 3][srow] = wv.w;
        __syncthreads();
        if (k0 + 8 < K) {
            if (ATMAP) {
                const __half* q = Abp + (size_t)(k0 + 8) * Nb;
                av.x = __half2float(q[0]);
                av.y = __half2float(q[Nb]);
                av.z = __half2float(q[2 * Nb]);
                av.w = __half2float(q[3 * Nb]);
            } else {
                av = *(const float4*)(Ap + k0 + 8);
            }
            wv = *(const float4*)(Wp + k0 + 8);
        }
#pragma unroll
        for (int kk = 0; kk < 8; kk++) {
            ulonglong2 a01 = *(const ulonglong2*)&As[kk][aoff];
            ulonglong2 a23 = *(const ulonglong2*)&As[kk][aoff + 4];
            float4 b0 = *(const float4*)&Bs[kk][boff];
            float4 b1 = *(const float4*)&Bs[kk][boff + 4];
            ull avv[4] = { a01.x, a01.y, a23.x, a23.y };
            ull bd[8];
            bd[0] = dup2(b0.x); bd[1] = dup2(b0.y);
            bd[2] = dup2(b0.z); bd[3] = dup2(b0.w);
            bd[4] = dup2(b1.x); bd[5] = dup2(b1.y);
            bd[6] = dup2(b1.z); bd[7] = dup2(b1.w);
#pragma unroll
            for (int i = 0; i < 4; i++)
#pragma unroll
                for (int j = 0; j < 8; j++)
                    acc[i][j] = ffma2(avv[i], bd[j], acc[i][j]);
        }
        __syncthreads();
    }

    float bb[8];
#pragma unroll
    for (int j = 0; j < 8; j++) bb[j] = bias[n0 + boff + j];

#pragma unroll
    for (int i = 0; i < 4; i++) {
        float o0[8], o1[8];
#pragma unroll
        for (int j = 0; j < 8; j++) {
            float2 u = unpack2(acc[i][j]);
            float x0 = u.x + bb[j], x1 = u.y + bb[j];
            if (RET) { x0 = retanh(x0); x1 = retanh(x1); }
            o0[j] = x0; o1[j] = x1;
        }
        int r0 = m0 + aoff + 2 * i;
        int r1 = r0 + 1;
        int cr0 = r0, cr1 = r1;
        if (CMAP) {
            cr0 = (r0 & 63) * Tt + (r0 >> 6);
            cr1 = (r1 & 63) * Tt + (r1 >> 6);
        }
        float4* p0 = (float4*)(C + (size_t)cr0 * Nc + n0 + boff);
        p0[0] = make_float4(o0[0], o0[1], o0[2], o0[3]);
        p0[1] = make_float4(o0[4], o0[5], o0[6], o0[7]);
        float4* p1 = (float4*)(C + (size_t)cr1 * Nc + n0 + boff);
        p1[0] = make_float4(o1[0], o1[1], o1[2], o1[3]);
        p1[1] = make_float4(o1[4], o1[5], o1[6], o1[7]);
    }
}

// ---------------- persistent RNN v9: fp16 h-state, fp32 math ----------------
// 128 CTAs x 256 thr, CTA gh owns 8 h cols; W (8h x 1024k fp32) in smem once.
// Thread (kw=warp, km2=lane>>3, ng=lane&7): 4 k-rows per chunk x 8 h x 8 n.
// Chunk = contiguous 16KB of fp16 hsT[t-1] ([128k][64n] rows of 128B).
// acc = 8h x 4 n-pairs f32x2. Reduce in fp32 via smem. Tree barrier/step.
#define CHUNK_B 16384
#define WSM_FLOATS 8192
#define RED_ROW_ULL 258
#define RNN_SMEM_BYTES (4 * CHUNK_B + WSM_FLOATS * 4 + 32 * RED_ROW_ULL * 8) // 164352

__global__ void __launch_bounds__(256, 1) rnn_persistent(
    const __half* __restrict__ h0T, const float* __restrict__ Wh,
    const float* __restrict__ bh, const float* __restrict__ inpT,
    __half* __restrict__ hsT)
{
    extern __shared__ float sm[];
    char* bufc = (char*)sm;                         // 4 x 16KB fp16 chunks
    float* Wsm = sm + 4 * CHUNK_B / 4;              // [k][8h]
    ull* red = (ull*)(Wsm + WSM_FLOATS);            // [32][258]

    const int tid = threadIdx.x;
    const int bx = blockIdx.x;
    const int gh = bx;
    const int kw = tid >> 5;
    const int lane = tid & 31;
    const int km2 = lane >> 3;
    const int ng = lane & 7;

    // stage W once: Wsm[k*8+h] = Wh[gh*8+h][k]
    for (int idx = tid; idx < 8192; idx += 256) {
        int h = idx >> 10;
        int k = idx & 1023;
        Wsm[k * 8 + h] = Wh[(size_t)(gh * 8 + h) * Hh + k];
    }
    __syncthreads();

    // epilogue mapping: warp h_o, lane ln -> n-pair ln (n0 = 2*ln)
    const int h_o = tid >> 5;
    const int ln = tid & 31;
    const int hout = gh * 8 + h_o;
    const float bia = bh[hout];
    const int prow = kw * 4 + km2;

    unsigned gen = 0;

    for (int t = 0; t < Tt; ++t) {
        const char* hp = (const char*)(t ? (hsT + (size_t)(t - 1) * NH) : h0T);

        ull acc[8][4];
#pragma unroll
        for (int h = 0; h < 8; h++)
#pragma unroll
            for (int p = 0; p < 4; p++) acc[h][p] = 0ull;

        // prologue: stage chunks 0,1,2 (16KB each; 4x16B per thread)
#pragma unroll
        for (int c = 0; c < 3; c++) {
            char* dst = bufc + (c & 3) * CHUNK_B;
            const char* src = hp + c * CHUNK_B;
#pragma unroll
            for (int j = 0; j < 4; j++) {
                int off = (j * 256 + tid) * 16;
                CP_ASYNC16(smem_u32(dst + off), src + off);
            }
            CP_COMMIT();
        }

#pragma unroll
        for (int c = 0; c < 8; c++) {
            cp_wait_n(c < 5 ? 2 : 7 - c);
            __syncthreads();
            if (c + 3 < 8) {
                char* dst = bufc + ((c + 3) & 3) * CHUNK_B;
                const char* src = hp + (c + 3) * CHUNK_B;
#pragma unroll
                for (int j = 0; j < 4; j++) {
                    int off = (j * 256 + tid) * 16;
                    CP_ASYNC16(smem_u32(dst + off), src + off);
                }
                CP_COMMIT();
            }
            const char* cur = bufc + (c & 3) * CHUNK_B;
#pragma unroll
            for (int i = 0; i < 4; i++) {
                int krow = kw * 16 + km2 * 4 + i;
                uint4 hv = *(const uint4*)(cur + krow * 128 + ng * 16);
                const float* wp = Wsm + (c * 128 + krow) * 8;
                float4 wa = *(const float4*)(wp);
                float4 wb = *(const float4*)(wp + 4);
                ull a0 = hf2f(hv.x), a1 = hf2f(hv.y), a2 = hf2f(hv.z), a3 = hf2f(hv.w);
                float wf[8] = { wa.x, wa.y, wa.z, wa.w, wb.x, wb.y, wb.z, wb.w };
#pragma unroll
                for (int h = 0; h < 8; h++) {
                    ull wd = dup2(wf[h]);
                    acc[h][0] = ffma2(a0, wd, acc[h][0]);
                    acc[h][1] = ffma2(a1, wd, acc[h][1]);
                    acc[h][2] = ffma2(a2, wd, acc[h][2]);
                    acc[h][3] = ffma2(a3, wd, acc[h][3]);
                }
            }
        }

        // partials -> smem: red[prow][h*32 + ng*4 + p]
        {
            ull* rb = red + (size_t)prow * RED_ROW_ULL + ng * 4;
#pragma unroll
            for (int h = 0; h < 8; h++) {
                *(ulonglong2*)(rb + h * 32)     = make_ulonglong2(acc[h][0], acc[h][1]);
                *(ulonglong2*)(rb + h * 32 + 2) = make_ulonglong2(acc[h][2], acc[h][3]);
            }
        }
        float2 ip = *(const float2*)(inpT + (size_t)t * NH + (size_t)hout * Nb + 2 * ln);
        __syncthreads();

        // final 32-way k reduce
        ull s = 0ull;
#pragma unroll
        for (int p = 0; p < 32; p++)
            s = addf2(s, red[(size_t)p * RED_ROW_ULL + h_o * 32 + ln]);
        float2 u = unpack2(s);
        float r0 = retanh(u.x + ip.x + bia);
        float r1 = retanh(u.y + ip.y + bia);

        // fp16x2 store (warp writes 128B)
        __half2 pk = __floats2half2_rn(r0, r1);
        *((unsigned*)(hsT + (size_t)t * NH + (size_t)hout * Nb) + ln) =
            *reinterpret_cast<unsigned*>(&pk);

        tree_barrier(bx, ++gen);
    }
}

// ---------------- host ----------------
extern "C" void kernel_launch(void* const* d_in, const int* in_sizes, int n_in,
                              void* d_out, int out_size)
{
    const float* data = (const float*)d_in[0];
    const float* h0v  = (const float*)d_in[1];
    const float* h0m  = (const float*)d_in[2];
    const float* Wi   = (const float*)d_in[3];
    const float* bi   = (const float*)d_in[4];
    const float* Wh   = (const float*)d_in[5];
    const float* bh   = (const float*)d_in[6];
    const float* Wo   = (const float*)d_in[7];
    const float* bo   = (const float*)d_in[8];
    const float* Wt   = (const float*)d_in[9];
    const float* bt   = (const float*)d_in[10];
    const float* Wi2  = (const float*)d_in[11];
    const float* bi2  = (const float*)d_in[12];
    const float* Wh2  = (const float*)d_in[13];
    const float* bh2  = (const float*)d_in[14];
    const float* Wo2  = (const float*)d_in[15];
    const float* bo2  = (const float*)d_in[16];
    float* out = (float*)d_out;

    float *nmaj, *inpT, *tmp, *outt;
    __half *hsT, *h0T, *h0T2;
    cudaGetSymbolAddress((void**)&nmaj, g_nmaj);
    cudaGetSymbolAddress((void**)&inpT, g_inpT);
    cudaGetSymbolAddress((void**)&hsT,  g_hsT);
    cudaGetSymbolAddress((void**)&tmp,  g_tmp);
    cudaGetSymbolAddress((void**)&outt, g_out_t);
    cudaGetSymbolAddress((void**)&h0T,  g_h0T);
    cudaGetSymbolAddress((void**)&h0T2, g_h0T2);

    cudaFuncSetAttribute(rnn_persistent,
                         cudaFuncAttributeMaxDynamicSharedMemorySize, RNN_SMEM_BYTES);

    dim3 blk(256);
    dim3 tgrid(Tt, Hh / 32);

    transpose_h0<<<256, blk>>>(h0v, h0T);                                          // 0
    transpose_h0<<<256, blk>>>(h0m, h0T2);                                         // 1
    gemm128<1, 0, 0, 0><<<dim3(MROWS / 128, Hh / 128), blk>>>(data, Wi, bi, nmaj, MROWS, Hh, Ii); // 2
    transpose_inp<<<tgrid, blk>>>(nmaj, inpT);                                     // 3
    reset_barrier_kernel<<<1, 512>>>();                                            // 4
    rnn_persistent<<<RNN_NCTA, blk, RNN_SMEM_BYTES>>>(h0T, Wh, bh, inpT, hsT);     // 5

    gemm128<0, 1, 0, 0><<<dim3(MROWS / 128, Oo / 128), blk>>>((const float*)hsT, Wo, bo, tmp, MROWS, Oo, Hh);
    gemm128<0, 0, 0, 1><<<dim3(MROWS / 128, Oo / 128), blk>>>(tmp, Wt, bt, outt, MROWS, Oo, Oo);
    gemm128<0, 0, 0, 0><<<dim3(MROWS / 128, Hh / 128), blk>>>(outt, Wi2, bi2, nmaj, MROWS, Hh, Oo);
    transpose_inp<<<tgrid, blk>>>(nmaj, inpT);
    reset_barrier_kernel<<<1, 512>>>();
    rnn_persistent<<<RNN_NCTA, blk, RNN_SMEM_BYTES>>>(h0T2, Wh2, bh2, inpT, hsT);
    gemm128<0, 1, 1, 0><<<dim3(MROWS / 128, Oo / 128), blk>>>((const float*)hsT, Wo2, bo2, out, MROWS, Oo, Hh);
}

// round 13
// speedup vs baseline: 1.1851x; 1.1851x over previous
#include <cuda_runtime.h>
#include <cuda_fp16.h>
#include <math.h>

// Problem dims
#define Nb 64
#define Tt 512
#define Ii 512
#define Hh 1024
#define Oo 512
#define MROWS (Nb*Tt)
#define NH (Nb*Hh)
#define RNN_NCTA 128

typedef unsigned long long ull;

// ---------------- scratch ----------------
__device__ float g_nmaj [(size_t)Tt * NH];      // n-major staging [T][N][H]
__device__ float g_inpT [(size_t)Tt * NH];      // transposed inp [T][H][64]
__device__ float g_hsT  [(size_t)Tt * NH];      // fp32 transposed h [T][1024][64]
__device__ float g_tmp  [(size_t)Tt * Nb * Oo];
__device__ float g_out_t[(size_t)Tt * Nb * Oo];
__device__ float g_h0T  [NH];
__device__ float g_h0T2 [NH];
__device__ unsigned g_l1[16 * 32];
__device__ unsigned g_l2;
__device__ volatile unsigned g_gen[16 * 32];

// ---------------- helpers ----------------
__device__ __forceinline__ ull ffma2(ull a, ull b, ull c) {
    ull d;
    asm("fma.rn.f32x2 %0, %1, %2, %3;" : "=l"(d) : "l"(a), "l"(b), "l"(c));
    return d;
}
__device__ __forceinline__ ull addf2(ull a, ull b) {
    ull d;
    asm("add.rn.f32x2 %0, %1, %2;" : "=l"(d) : "l"(a), "l"(b));
    return d;
}
__device__ __forceinline__ float2 unpack2(ull v) {
    float2 r;
    asm("mov.b64 {%0, %1}, %2;" : "=f"(r.x), "=f"(r.y) : "l"(v));
    return r;
}
__device__ __forceinline__ ull dup2(float v) {
    ull r;
    asm("mov.b64 %0, {%1, %1};" : "=l"(r) : "f"(v));
    return r;
}
__device__ __forceinline__ float retanh(float x) {
    return x > 0.f ? tanhf(x) : 0.f;
}
__device__ __forceinline__ unsigned smem_u32(const void* p) {
    return (unsigned)__cvta_generic_to_shared(p);
}
#define CP_ASYNC16(dst, src) \
    asm volatile("cp.async.cg.shared.global [%0], [%1], 16;" :: "r"(dst), "l"(src))
#define CP_COMMIT() asm volatile("cp.async.commit_group;" ::: "memory")
__device__ __forceinline__ void cp_wait_n(int n) {
    if (n == 0)      asm volatile("cp.async.wait_group 0;" ::: "memory");
    else if (n == 1) asm volatile("cp.async.wait_group 1;" ::: "memory");
    else             asm volatile("cp.async.wait_group 2;" ::: "memory");
}
#define LDSM_X4(r0, r1, r2, r3, addr) \
    asm volatile("ldmatrix.sync.aligned.m8n8.x4.shared.b16 {%0,%1,%2,%3}, [%4];" \
        : "=r"(r0), "=r"(r1), "=r"(r2), "=r"(r3) : "r"(addr))
#define MMA16816(c0, c1, c2, c3, a0, a1, a2, a3, b0, b1) \
    asm volatile("mma.sync.aligned.m16n8k16.row.col.f32.f16.f16.f32 " \
        "{%0,%1,%2,%3}, {%4,%5,%6,%7}, {%8,%9}, {%0,%1,%2,%3};" \
        : "+f"(c0), "+f"(c1), "+f"(c2), "+f"(c3) \
        : "r"(a0), "r"(a1), "r"(a2), "r"(a3), "r"(b0), "r"(b1))

__device__ __forceinline__ uint4 pack8h(float4 a, float4 b) {
    __half2 h0 = __floats2half2_rn(a.x, a.y);
    __half2 h1 = __floats2half2_rn(a.z, a.w);
    __half2 h2 = __floats2half2_rn(b.x, b.y);
    __half2 h3 = __floats2half2_rn(b.z, b.w);
    uint4 u;
    u.x = *reinterpret_cast<unsigned*>(&h0);
    u.y = *reinterpret_cast<unsigned*>(&h1);
    u.z = *reinterpret_cast<unsigned*>(&h2);
    u.w = *reinterpret_cast<unsigned*>(&h3);
    return u;
}

__global__ void reset_barrier_kernel() {
    int t = threadIdx.x;
    if (t < 16 * 32) { g_l1[t] = 0u; g_gen[t] = 0u; }
    if (t == 0) g_l2 = 0u;
}

// tree arrival + fan-out release (16 gen lines, 8 pollers each)
__device__ __forceinline__ void tree_barrier(int bx, unsigned target) {
    __syncthreads();
    if (threadIdx.x == 0) {
        __threadfence();
        unsigned o1 = atomicAdd(&g_l1[(bx >> 3) * 32], 1u);
        if ((o1 & 7u) == 7u) {
            unsigned o2 = atomicAdd(&g_l2, 1u);
            if ((o2 & 15u) == 15u) {
                __threadfence();
#pragma unroll
                for (int g = 0; g < 16; g++) g_gen[g * 32] = target;
            }
        }
        while (g_gen[(bx >> 3) * 32] < target) { }
        __threadfence();
    }
    __syncthreads();
}

// h0 [N][H] -> [H][64]
__global__ void transpose64x1024(const float* __restrict__ in, float* __restrict__ out) {
    int i = blockIdx.x * 256 + threadIdx.x;
    int h = i >> 6, n = i & 63;
    out[i] = in[n * Hh + h];
}

// inp [T][N][H] -> [T][H][64]
__global__ void __launch_bounds__(256) transpose_inp(
    const float* __restrict__ in, float* __restrict__ out)
{
    __shared__ float s[32][65];
    const int t = blockIdx.x;
    const int h0 = blockIdx.y * 32;
    const int tid = threadIdx.x;
    const float* ip = in + (size_t)t * NH;
    float* op = out + (size_t)t * NH;

    int hl = tid & 31;
    int nb = tid >> 5;
#pragma unroll
    for (int i = 0; i < 8; i++) {
        int n = nb * 8 + i;
        s[hl][n] = ip[(size_t)n * Hh + h0 + hl];
    }
    __syncthreads();
    int n4 = (tid & 15) * 4;
    int hr = tid >> 4;
#pragma unroll
    for (int i = 0; i < 2; i++) {
        int h = hr * 2 + i;
        float4 v = make_float4(s[h][n4], s[h][n4 + 1], s[h][n4 + 2], s[h][n4 + 3]);
        *(float4*)(op + (size_t)(h0 + h) * Nb + n4) = v;
    }
}

// ---------------- HMMA GEMM: C = act(A * W^T + bias), fp16 inputs / fp32 accum
// CTA tile 128m x 64n, BK=32. 8 warps = 2m x 4n; warp tile 64m x 16n.
// A/W loaded fp32 (AMAP/ATMAP gathers as before), converted to fp16 in staging.
// Smem rows stride 56 halfs (112B) -> conflict-free LDSM wavefronts.
#define XS 56
template<int AMAP, int ATMAP, int CMAP, int RET>
__global__ void __launch_bounds__(256, 2) hgemm(
    const float* __restrict__ A, const float* __restrict__ W,
    const float* __restrict__ bias, float* __restrict__ C,
    int M, int Nc, int K)
{
    __shared__ alignas(16) __half As[128 * XS];
    __shared__ alignas(16) __half Bs[64 * XS];

    const int tid = threadIdx.x;
    const int m0 = blockIdx.x * 128;
    const int n0 = blockIdx.y * 64;
    const int warp = tid >> 5;
    const int lane = tid & 31;
    const int wm = warp & 1;
    const int wn = warp >> 1;

    const int sr = tid >> 1;         // A staging row 0..127
    const int kh = tid & 1;          // k-half (16 floats)

    int r = m0 + sr;
    const float* Ap;
    if (AMAP) {
        int nn = r & 63, tt = r >> 6;
        Ap = A + (size_t)(nn * Tt + tt) * K + kh * 16;
    } else if (ATMAP) {
        Ap = A + (size_t)(r >> 6) * K * Nb + (r & 63) + (size_t)(kh * 16) * Nb;
    } else {
        Ap = A + (size_t)r * K + kh * 16;
    }
    const float* Wp = W + (size_t)(n0 + sr) * K + kh * 16;   // valid for tid < 128

    float acc[4][2][4];
#pragma unroll
    for (int mt = 0; mt < 4; mt++)
#pragma unroll
        for (int nt = 0; nt < 2; nt++)
#pragma unroll
            for (int c = 0; c < 4; c++) acc[mt][nt][c] = 0.f;

    float4 ra[4], rw[4];
    // prefetch k0 = 0
    if (ATMAP) {
#pragma unroll
        for (int j = 0; j < 4; j++) {
            const float* q = Ap + (size_t)(4 * j) * Nb;
            ra[j] = make_float4(q[0], q[Nb], q[2 * Nb], q[3 * Nb]);
        }
    } else {
#pragma unroll
        for (int j = 0; j < 4; j++) ra[j] = *(const float4*)(Ap + 4 * j);
    }
    if (tid < 128) {
#pragma unroll
        for (int j = 0; j < 4; j++) rw[j] = *(const float4*)(Wp + 4 * j);
    }

    const int rl = lane & 15;
    const int koff = (lane >> 4) * 8;

    for (int k0 = 0; k0 < K; k0 += 32) {
        // stage (convert to fp16)
        *(uint4*)(As + sr * XS + kh * 16)     = pack8h(ra[0], ra[1]);
        *(uint4*)(As + sr * XS + kh * 16 + 8) = pack8h(ra[2], ra[3]);
        if (tid < 128) {
            *(uint4*)(Bs + sr * XS + kh * 16)     = pack8h(rw[0], rw[1]);
            *(uint4*)(Bs + sr * XS + kh * 16 + 8) = pack8h(rw[2], rw[3]);
        }
        __syncthreads();
        if (k0 + 32 < K) {
            if (ATMAP) {
                const float* base = Ap + (size_t)(k0 + 32) * Nb;
#pragma unroll
                for (int j = 0; j < 4; j++) {
                    const float* q = base + (size_t)(4 * j) * Nb;
                    ra[j] = make_float4(q[0], q[Nb], q[2 * Nb], q[3 * Nb]);
                }
            } else {
#pragma unroll
                for (int j = 0; j < 4; j++) ra[j] = *(const float4*)(Ap + k0 + 32 + 4 * j);
            }
            if (tid < 128) {
#pragma unroll
                for (int j = 0; j < 4; j++) rw[j] = *(const float4*)(Wp + k0 + 32 + 4 * j);
            }
        }
#pragma unroll
        for (int ks = 0; ks < 32; ks += 16) {
            unsigned bf0, bf1, bf2, bf3;
            unsigned baddr = smem_u32(Bs + (wn * 16 + rl) * XS + ks + koff);
            LDSM_X4(bf0, bf1, bf2, bf3, baddr);
#pragma unroll
            for (int mt = 0; mt < 4; mt++) {
                unsigned a0, a1, a2, a3;
                unsigned aaddr = smem_u32(As + (wm * 64 + mt * 16 + rl) * XS + ks + koff);
                LDSM_X4(a0, a1, a2, a3, aaddr);
                MMA16816(acc[mt][0][0], acc[mt][0][1], acc[mt][0][2], acc[mt][0][3],
                         a0, a1, a2, a3, bf0, bf2);
                MMA16816(acc[mt][1][0], acc[mt][1][1], acc[mt][1][2], acc[mt][1][3],
                         a0, a1, a2, a3, bf1, bf3);
            }
        }
        __syncthreads();
    }

    // epilogue
    const int gr = lane >> 2;
    const int tc = lane & 3;
#pragma unroll
    for (int mt = 0; mt < 4; mt++) {
#pragma unroll
        for (int nt = 0; nt < 2; nt++) {
            int row0 = m0 + wm * 64 + mt * 16 + gr;
            int col = n0 + wn * 16 + nt * 8 + tc * 2;
            float b0 = bias[col], b1 = bias[col + 1];
            float x0 = acc[mt][nt][0] + b0, x1 = acc[mt][nt][1] + b1;
            float x2 = acc[mt][nt][2] + b0, x3 = acc[mt][nt][3] + b1;
            if (RET) { x0 = retanh(x0); x1 = retanh(x1); x2 = retanh(x2); x3 = retanh(x3); }
            int r0 = row0, r1 = row0 + 8;
            if (CMAP) {
                r0 = (row0 & 63) * Tt + (row0 >> 6);
                int rw2 = row0 + 8;
                r1 = (rw2 & 63) * Tt + (rw2 >> 6);
            }
            *(float2*)(C + (size_t)r0 * Nc + col) = make_float2(x0, x1);
            *(float2*)(C + (size_t)r1 * Nc + col) = make_float2(x2, x3);
        }
    }
}

// ---------------- persistent RNN v7 (R10, fp32): hT=8, W-in-smem, depth-3 ------
#define CHUNK_FLOATS 8192
#define WSM_FLOATS 8192
#define RED_ROW_ULL 258
#define RNN_SMEM_BYTES ((4 * CHUNK_FLOATS + WSM_FLOATS) * 4 + 32 * RED_ROW_ULL * 8) // 229888

__global__ void __launch_bounds__(256, 1) rnn_persistent(
    const float* __restrict__ h0T, const float* __restrict__ Wh,
    const float* __restrict__ bh, const float* __restrict__ inpT,
    float* __restrict__ hsT)
{
    extern __shared__ float sm[];
    float* bufs = sm;
    float* Wsm  = sm + 4 * CHUNK_FLOATS;
    ull* red    = (ull*)(sm + 4 * CHUNK_FLOATS + WSM_FLOATS);

    const int tid = threadIdx.x;
    const int bx = blockIdx.x;
    const int gh = bx;
    const int kw = tid >> 5;
    const int lane = tid & 31;
    const int km2 = lane >> 3;
    const int ng = lane & 7;

    for (int idx = tid; idx < 8192; idx += 256) {
        int h = idx >> 10;
        int k = idx & 1023;
        Wsm[k * 8 + h] = Wh[(size_t)(gh * 8 + h) * Hh + k];
    }
    __syncthreads();

    const int h_o = tid >> 5;
    const int ln = tid & 31;
    const int hout = gh * 8 + h_o;
    const int ej = ln & 3;
    const int eng = ln >> 2;
    const int n0 = (ej >> 1) * 32 + eng * 4 + (ej & 1) * 2;
    const float bia = bh[hout];
    const int prow = kw * 4 + km2;

    unsigned gen = 0;

    for (int t = 0; t < Tt; ++t) {
        const float* hp = t ? (hsT + (size_t)(t - 1) * NH) : h0T;

        ull acc[8][4];
#pragma unroll
        for (int h = 0; h < 8; h++)
#pragma unroll
            for (int p = 0; p < 4; p++) acc[h][p] = 0ull;

#pragma unroll
        for (int c = 0; c < 3; c++) {
            float* dst = bufs + (c & 3) * CHUNK_FLOATS;
            const float* src = hp + c * CHUNK_FLOATS;
#pragma unroll
            for (int j = 0; j < 8; j++) {
                int off = j * 1024 + tid * 4;
                CP_ASYNC16(smem_u32(dst + off), src + off);
            }
            CP_COMMIT();
        }

#pragma unroll
        for (int c = 0; c < 8; c++) {
            cp_wait_n(c < 5 ? 2 : 7 - c);
            __syncthreads();
            if (c + 3 < 8) {
                float* dst = bufs + ((c + 3) & 3) * CHUNK_FLOATS;
                const float* src = hp + (c + 3) * CHUNK_FLOATS;
#pragma unroll
                for (int j = 0; j < 8; j++) {
                    int off = j * 1024 + tid * 4;
                    CP_ASYNC16(smem_u32(dst + off), src + off);
                }
                CP_COMMIT();
            }
            const float* cur = bufs + (c & 3) * CHUNK_FLOATS;
#pragma unroll
            for (int i = 0; i < 4; i++) {
                int krow = kw * 16 + km2 * 4 + i;
                const float* row = cur + krow * 64;
                const float* wp = Wsm + (c * 128 + krow) * 8;
                float4 wa = *(const float4*)(wp);
                float4 wb = *(const float4*)(wp + 4);
                ulonglong2 A = *(const ulonglong2*)(row + ng * 4);
                ulonglong2 B = *(const ulonglong2*)(row + 32 + ng * 4);
                float wf[8] = { wa.x, wa.y, wa.z, wa.w, wb.x, wb.y, wb.z, wb.w };
#pragma unroll
                for (int h = 0; h < 8; h++) {
                    ull wd = dup2(wf[h]);
                    acc[h][0] = ffma2(A.x, wd, acc[h][0]);
                    acc[h][1] = ffma2(A.y, wd, acc[h][1]);
                    acc[h][2] = ffma2(B.x, wd, acc[h][2]);
                    acc[h][3] = ffma2(B.y, wd, acc[h][3]);
                }
            }
        }

        {
            ull* rb = red + (size_t)prow * RED_ROW_ULL + ng * 4;
#pragma unroll
            for (int h = 0; h < 8; h++) {
                *(ulonglong2*)(rb + h * 32)     = make_ulonglong2(acc[h][0], acc[h][1]);
                *(ulonglong2*)(rb + h * 32 + 2) = make_ulonglong2(acc[h][2], acc[h][3]);
            }
        }
        float2 ip = *(const float2*)(inpT + (size_t)t * NH + (size_t)hout * Nb + n0);
        __syncthreads();

        ull s = 0ull;
#pragma unroll
        for (int p = 0; p < 32; p++)
            s = addf2(s, red[(size_t)p * RED_ROW_ULL + h_o * 32 + ln]);
        float2 u = unpack2(s);
        float r0 = retanh(u.x + ip.x + bia);
        float r1 = retanh(u.y + ip.y + bia);

        *(float2*)(hsT + (size_t)t * NH + (size_t)hout * Nb + n0) = make_float2(r0, r1);

        tree_barrier(bx, ++gen);
    }
}

// ---------------- host ----------------
extern "C" void kernel_launch(void* const* d_in, const int* in_sizes, int n_in,
                              void* d_out, int out_size)
{
    const float* data = (const float*)d_in[0];
    const float* h0v  = (const float*)d_in[1];
    const float* h0m  = (const float*)d_in[2];
    const float* Wi   = (const float*)d_in[3];
    const float* bi   = (const float*)d_in[4];
    const float* Wh   = (const float*)d_in[5];
    const float* bh   = (const float*)d_in[6];
    const float* Wo   = (const float*)d_in[7];
    const float* bo   = (const float*)d_in[8];
    const float* Wt   = (const float*)d_in[9];
    const float* bt   = (const float*)d_in[10];
    const float* Wi2  = (const float*)d_in[11];
    const float* bi2  = (const float*)d_in[12];
    const float* Wh2  = (const float*)d_in[13];
    const float* bh2  = (const float*)d_in[14];
    const float* Wo2  = (const float*)d_in[15];
    const float* bo2  = (const float*)d_in[16];
    float* out = (float*)d_out;

    float *nmaj, *inpT, *hsT, *tmp, *outt, *h0T, *h0T2;
    cudaGetSymbolAddress((void**)&nmaj, g_nmaj);
    cudaGetSymbolAddress((void**)&inpT, g_inpT);
    cudaGetSymbolAddress((void**)&hsT,  g_hsT);
    cudaGetSymbolAddress((void**)&tmp,  g_tmp);
    cudaGetSymbolAddress((void**)&outt, g_out_t);
    cudaGetSymbolAddress((void**)&h0T,  g_h0T);
    cudaGetSymbolAddress((void**)&h0T2, g_h0T2);

    cudaFuncSetAttribute(rnn_persistent,
                         cudaFuncAttributeMaxDynamicSharedMemorySize, RNN_SMEM_BYTES);

    dim3 blk(256);
    dim3 tgrid(Tt, Hh / 32);

    transpose64x1024<<<256, blk>>>(h0v, h0T);                                      // 0
    transpose64x1024<<<256, blk>>>(h0m, h0T2);                                     // 1
    hgemm<1, 0, 0, 0><<<dim3(MROWS / 128, Hh / 64), blk>>>(data, Wi, bi, nmaj, MROWS, Hh, Ii); // 2
    transpose_inp<<<tgrid, blk>>>(nmaj, inpT);                                     // 3
    reset_barrier_kernel<<<1, 512>>>();                                            // 4
    rnn_persistent<<<RNN_NCTA, blk, RNN_SMEM_BYTES>>>(h0T, Wh, bh, inpT, hsT);     // 5

    hgemm<0, 1, 0, 0><<<dim3(MROWS / 128, Oo / 64), blk>>>(hsT, Wo, bo, tmp, MROWS, Oo, Hh);
    hgemm<0, 0, 0, 1><<<dim3(MROWS / 128, Oo / 64), blk>>>(tmp, Wt, bt, outt, MROWS, Oo, Oo);
    hgemm<0, 0, 0, 0><<<dim3(MROWS / 128, Hh / 64), blk>>>(outt, Wi2, bi2, nmaj, MROWS, Hh, Oo);
    transpose_inp<<<tgrid, blk>>>(nmaj, inpT);
    reset_barrier_kernel<<<1, 512>>>();
    rnn_persistent<<<RNN_NCTA, blk, RNN_SMEM_BYTES>>>(h0T2, Wh2, bh2, inpT, hsT);
    hgemm<0, 1, 1, 0><<<dim3(MROWS / 128, Oo / 64), blk>>>(hsT, Wo2, bo2, out, MROWS, Oo, Hh);
}